// round 14
// baseline (speedup 1.0000x reference)
#include <cuda_runtime.h>

#define NS 4096
#define NBATCH 32
#define TPB 256

// pywt db4 dec filters, time-reversed (cross-correlation form)
__device__ __constant__ float cH0[8] = {
     0.23037781330885523f,  0.7148465705525415f,   0.6308807679295904f,
    -0.02798376941698385f, -0.18703481171888114f,  0.030841381835986965f,
     0.032883011666982945f, -0.010597401784997278f };
__device__ __constant__ float cH1[8] = {
    -0.010597401784997278f, -0.032883011666982945f, 0.030841381835986965f,
     0.18703481171888114f,  -0.02798376941698385f,  -0.6308807679295904f,
     0.7148465705525415f,   -0.23037781330885523f };

// Lowpass scratch planes, (B, T_k, 64) contiguous.
__device__ float g_scratch[8126464];
#define OFF_LO1 0
#define OFF_LO2 4194304
#define OFF_LO3 6291456
#define OFF_LO4 7340032
#define OFF_LO5 7864320

__device__ __forceinline__ int level_of(float sc) {
    int l = 2 + (int)rintf(sc * 3.0f);          // round-half-even, matches jnp.round
    return l < 2 ? 2 : (l > 5 ? 5 : l);
}

// One analysis level. Asymmetric grid:
//   conv region : TOUT*16 threads/batch, 1 float4 each (proven mapping,
//                 MLP-8 branchless interior fast path)
//   tail region : (NS-TOUT)*4 threads/batch, each zeroing 4 consecutive
//                 float4 (64 B) of the detail-plane tail
template <int TIN>
__global__ void __launch_bounds__(TPB)
level_kernel(const float* __restrict__ in, float* __restrict__ loOut,
             float* __restrict__ det, const float* __restrict__ scores,
             int detIdx)
{
    constexpr int TOUT  = TIN / 2;
    constexpr int CONVN = TOUT * 16;             // conv threads per batch
    constexpr int TAILN = (NS - TOUT) * 4;       // fat tail threads per batch
    constexpr int PBT   = CONVN + TAILN;

    int idx = blockIdx.x * TPB + threadIdx.x;
    const int b   = idx / PBT;
    const int rem = idx - b * PBT;

    if (rem >= CONVN) {
        // ---- fat tail zero: 4 consecutive float4 of the detail tail ----
        const int u = rem - CONVN;               // 0 .. TAILN-1
        float4* p = (float4*)det + (size_t)b * (NS * 16) + CONVN + (size_t)u * 4;
        const float4 z = make_float4(0.f, 0.f, 0.f, 0.f);
        p[0] = z; p[1] = z; p[2] = z; p[3] = z;
        return;
    }

    const int f4 = rem & 15;
    const int n  = rem >> 4;

    const float4* pin = (const float4*)in + (size_t)b * TIN * 16 + f4;
    float4 lo = make_float4(0.f, 0.f, 0.f, 0.f);
    float4 hi = make_float4(0.f, 0.f, 0.f, 0.f);

    if (n >= 2 && n < TOUT - 2) {
        // branchless interior: base + immediate offsets, loads front-batched
        const float4* p0 = pin + (size_t)(2 * n - 3) * 16;
        float4 v[8];
#pragma unroll
        for (int t = 0; t < 8; ++t) v[t] = __ldg(p0 + t * 16);
#pragma unroll
        for (int t = 0; t < 8; ++t) {
            const float c0 = cH0[t], c1 = cH1[t];
            lo.x = fmaf(c0, v[t].x, lo.x); lo.y = fmaf(c0, v[t].y, lo.y);
            lo.z = fmaf(c0, v[t].z, lo.z); lo.w = fmaf(c0, v[t].w, lo.w);
            hi.x = fmaf(c1, v[t].x, hi.x); hi.y = fmaf(c1, v[t].y, hi.y);
            hi.z = fmaf(c1, v[t].z, hi.z); hi.w = fmaf(c1, v[t].w, hi.w);
        }
    } else {
#pragma unroll
        for (int t = 0; t < 8; ++t) {
            int r = 2 * n + t - 3;
            if (r >= 0 && r < TIN) {
                float4 v = __ldg(pin + (size_t)r * 16);
                const float c0 = cH0[t], c1 = cH1[t];
                lo.x = fmaf(c0, v.x, lo.x); lo.y = fmaf(c0, v.y, lo.y);
                lo.z = fmaf(c0, v.z, lo.z); lo.w = fmaf(c0, v.w, lo.w);
                hi.x = fmaf(c1, v.x, hi.x); hi.y = fmaf(c1, v.y, hi.y);
                hi.z = fmaf(c1, v.z, hi.z); hi.w = fmaf(c1, v.w, hi.w);
            }
        }
    }

    // per-feature activity mask: detail i populated iff i < lf (lf >= 2)
    if (detIdx >= 2) {
        const int f = f4 * 4;
        if (detIdx >= level_of(__ldg(scores + f + 0))) hi.x = 0.f;
        if (detIdx >= level_of(__ldg(scores + f + 1))) hi.y = 0.f;
        if (detIdx >= level_of(__ldg(scores + f + 2))) hi.z = 0.f;
        if (detIdx >= level_of(__ldg(scores + f + 3))) hi.w = 0.f;
    }

    ((float4*)loOut)[((size_t)b * TOUT + n) * 16 + f4] = lo;
    ((float4*)det)[((size_t)b * NS + n) * 16 + f4] = hi;
}

// Final: approx (plane 0), high_freq (plane 6), low_freq (plane 7).
__global__ void __launch_bounds__(TPB)
final_kernel(float* __restrict__ out, const float* __restrict__ scores)
{
    int idx = blockIdx.x * TPB + threadIdx.x;
    const int f4 = idx & 15;
    const int s  = (idx >> 4) & (NS - 1);
    const int b  = idx >> 16;

    const size_t PLANE4 = (size_t)NBATCH * NS * 16;      // float4 units
    const size_t row4   = ((size_t)b * NS + s) * 16 + f4;

    // high_freq = sum of masked detail prefixes (det_k zero for s >= T_k)
    float4 h = make_float4(0.f, 0.f, 0.f, 0.f);
#pragma unroll
    for (int i = 0; i < 5; ++i) {
        if (s < (2048 >> i)) {
            float4 d = __ldg((const float4*)out + (1 + i) * PLANE4 + row4);
            h.x += d.x; h.y += d.y; h.z += d.z; h.w += d.w;
        }
    }
    ((float4*)out)[6 * PLANE4 + row4] = h;

    // approx: per-feature selected lowpass level
    const size_t offs[4] = { OFF_LO2, OFF_LO3, OFF_LO4, OFF_LO5 };
    const int f = f4 * 4;
    float av[4];
#pragma unroll
    for (int j = 0; j < 4; ++j) {
        int k = level_of(__ldg(scores + f + j)) - 2;     // 0..3
        int T = 1024 >> k;
        av[j] = (s < T)
            ? __ldg(g_scratch + offs[k] + ((size_t)b * T + s) * 64 + f + j)
            : 0.f;
    }
    float4 a = make_float4(av[0], av[1], av[2], av[3]);
    ((float4*)out)[row4] = a;               // approx
    ((float4*)out)[7 * PLANE4 + row4] = a;  // low_freq
}

template <int TIN>
static inline void launch_level(const float* in, float* lo, float* det,
                                const float* scores, int detIdx)
{
    constexpr int PBT = (TIN / 2) * 16 + (NS - TIN / 2) * 4;
    const int total = NBATCH * PBT;
    level_kernel<TIN><<<(total + TPB - 1) / TPB, TPB>>>(in, lo, det, scores, detIdx);
}

extern "C" void kernel_launch(void* const* d_in, const int* in_sizes, int n_in,
                              void* d_out, int out_size)
{
    const float* x      = (const float*)d_in[0];
    const float* scores = (const float*)d_in[1];
    float* out          = (float*)d_out;

    float* scratch;
    cudaGetSymbolAddress((void**)&scratch, g_scratch);
    float* lo1 = scratch + OFF_LO1;
    float* lo2 = scratch + OFF_LO2;
    float* lo3 = scratch + OFF_LO3;
    float* lo4 = scratch + OFF_LO4;
    float* lo5 = scratch + OFF_LO5;

    const size_t PLANE = (size_t)NBATCH * NS * 64;

    launch_level<4096>(x,   lo1, out + 1 * PLANE, scores, 0);
    launch_level<2048>(lo1, lo2, out + 2 * PLANE, scores, 1);
    launch_level<1024>(lo2, lo3, out + 3 * PLANE, scores, 2);
    launch_level< 512>(lo3, lo4, out + 4 * PLANE, scores, 3);
    launch_level< 256>(lo4, lo5, out + 5 * PLANE, scores, 4);
    final_kernel<<<(NBATCH * NS * 16) / TPB, TPB>>>(out, scores);
}

// round 15
// speedup vs baseline: 1.0712x; 1.0712x over previous
#include <cuda_runtime.h>

#define NS 4096
#define NBATCH 32
#define TPB 256

// pywt db4 dec filters, time-reversed (cross-correlation form)
__device__ __constant__ float cH0[8] = {
     0.23037781330885523f,  0.7148465705525415f,   0.6308807679295904f,
    -0.02798376941698385f, -0.18703481171888114f,  0.030841381835986965f,
     0.032883011666982945f, -0.010597401784997278f };
__device__ __constant__ float cH1[8] = {
    -0.010597401784997278f, -0.032883011666982945f, 0.030841381835986965f,
     0.18703481171888114f,  -0.02798376941698385f,  -0.6308807679295904f,
     0.7148465705525415f,   -0.23037781330885523f };

// Composite (cascaded) filters over lo2:
//   depth-2 (lo4/det4): 22 taps, lo2 idx = 4m + u - 9
//   depth-3 (lo5/det5): 50 taps, lo2 idx = 8p + v - 21
__device__ float g_C2[22], g_D2[22], g_C3[50], g_D3[50];

// Lowpass scratch planes, (B, T_k, 64) contiguous.
__device__ float g_scratch[8126464];
#define OFF_LO1 0
#define OFF_LO2 4194304
#define OFF_LO3 6291456
#define OFF_LO4 7340032
#define OFF_LO5 7864320

__device__ __forceinline__ int level_of(float sc) {
    int l = 2 + (int)rintf(sc * 3.0f);          // round-half-even, matches jnp.round
    return l < 2 ? 2 : (l > 5 ? 5 : l);
}

__global__ void init_filters()
{
    if (threadIdx.x == 0) {
        float C2[22], D2[22];
        for (int u = 0; u < 22; ++u) { C2[u] = 0.f; D2[u] = 0.f; }
        for (int s = 0; s < 8; ++s)
            for (int t = 0; t < 8; ++t) {
                C2[2 * s + t] += cH0[s] * cH0[t];   // lo4  = H0(H0)
                D2[2 * s + t] += cH1[s] * cH0[t];   // det4 = H1(H0)
            }
        float C3[50], D3[50];
        for (int v = 0; v < 50; ++v) { C3[v] = 0.f; D3[v] = 0.f; }
        for (int r = 0; r < 8; ++r)
            for (int u = 0; u < 22; ++u) {
                C3[4 * r + u] += cH0[r] * C2[u];    // lo5  = H0(H0(H0))
                D3[4 * r + u] += cH1[r] * C2[u];    // det5 = H1(H0(H0))
            }
        for (int u = 0; u < 22; ++u) { g_C2[u] = C2[u]; g_D2[u] = D2[u]; }
        for (int v = 0; v < 50; ++v) { g_C3[v] = C3[v]; g_D3[v] = D3[v]; }
    }
}

// ---------------- levels 1 & 2: proven R13 kernel ----------------
template <int TIN>
__global__ void __launch_bounds__(TPB)
level_kernel(const float* __restrict__ in, float* __restrict__ loOut,
             float* __restrict__ det)
{
    const int TOUT = TIN / 2;
    int idx = blockIdx.x * TPB + threadIdx.x;      // (b, n, f4)
    const int f4 = idx & 15;
    const int n  = (idx >> 4) & (NS - 1);
    const int b  = idx >> 16;

    float4* pd = (float4*)det + ((size_t)b * NS + n) * 16 + f4;
    if (n >= TOUT) { *pd = make_float4(0.f, 0.f, 0.f, 0.f); return; }

    const float4* pin = (const float4*)in + (size_t)b * TIN * 16 + f4;
    float4 lo = make_float4(0.f, 0.f, 0.f, 0.f);
    float4 hi = make_float4(0.f, 0.f, 0.f, 0.f);

    if (n >= 2 && n < TOUT - 2) {
        const float4* p0 = pin + (size_t)(2 * n - 3) * 16;
        float4 v[8];
#pragma unroll
        for (int t = 0; t < 8; ++t) v[t] = __ldg(p0 + t * 16);
#pragma unroll
        for (int t = 0; t < 8; ++t) {
            const float c0 = cH0[t], c1 = cH1[t];
            lo.x = fmaf(c0, v[t].x, lo.x); lo.y = fmaf(c0, v[t].y, lo.y);
            lo.z = fmaf(c0, v[t].z, lo.z); lo.w = fmaf(c0, v[t].w, lo.w);
            hi.x = fmaf(c1, v[t].x, hi.x); hi.y = fmaf(c1, v[t].y, hi.y);
            hi.z = fmaf(c1, v[t].z, hi.z); hi.w = fmaf(c1, v[t].w, hi.w);
        }
    } else {
#pragma unroll
        for (int t = 0; t < 8; ++t) {
            int r = 2 * n + t - 3;
            if (r >= 0 && r < TIN) {
                float4 v = __ldg(pin + (size_t)r * 16);
                const float c0 = cH0[t], c1 = cH1[t];
                lo.x = fmaf(c0, v.x, lo.x); lo.y = fmaf(c0, v.y, lo.y);
                lo.z = fmaf(c0, v.z, lo.z); lo.w = fmaf(c0, v.w, lo.w);
                hi.x = fmaf(c1, v.x, hi.x); hi.y = fmaf(c1, v.y, hi.y);
                hi.z = fmaf(c1, v.z, hi.z); hi.w = fmaf(c1, v.w, hi.w);
            }
        }
    }
    // det1/det2 always active (lf >= 2): no mask
    ((float4*)loOut)[((size_t)b * TOUT + n) * 16 + f4] = lo;
    *pd = hi;
}

// ---------------- exact edge helpers (match cascade zero-padding) ----------------
__device__ __forceinline__ float4 f40() { return make_float4(0.f, 0.f, 0.f, 0.f); }

__device__ __forceinline__ float4 lo2_at(const float4* __restrict__ lo2b, int r) {
    return (r >= 0 && r < 1024) ? __ldg(lo2b + (size_t)r * 16) : f40();
}
__device__ float4 lo3_at(const float4* __restrict__ lo2b, int n) {
    if (n < 0 || n >= 512) return f40();
    float4 a = f40();
#pragma unroll
    for (int t = 0; t < 8; ++t) {
        float4 v = lo2_at(lo2b, 2 * n + t - 3);
        float c = cH0[t];
        a.x = fmaf(c, v.x, a.x); a.y = fmaf(c, v.y, a.y);
        a.z = fmaf(c, v.z, a.z); a.w = fmaf(c, v.w, a.w);
    }
    return a;
}
__device__ float4 lo4_at(const float4* __restrict__ lo2b, int m) {
    if (m < 0 || m >= 256) return f40();
    float4 a = f40();
#pragma unroll
    for (int s = 0; s < 8; ++s) {
        float4 v = lo3_at(lo2b, 2 * m + s - 3);
        float c = cH0[s];
        a.x = fmaf(c, v.x, a.x); a.y = fmaf(c, v.y, a.y);
        a.z = fmaf(c, v.z, a.z); a.w = fmaf(c, v.w, a.w);
    }
    return a;
}

// ---------------- levels 3+4+5 merged: composite filters over lo2 ----------------
// Grid covers 3 full detail planes: (b, k in {0,1,2}, n < 4096, f4).
__global__ void __launch_bounds__(TPB)
mega345_kernel(const float* __restrict__ lo2g, float* __restrict__ lo3g,
               float* __restrict__ lo4g, float* __restrict__ lo5g,
               float* __restrict__ out, const float* __restrict__ scores)
{
    int idx = blockIdx.x * TPB + threadIdx.x;
    const int f4 = idx & 15;
    const int n  = (idx >> 4) & (NS - 1);
    const int vv = idx >> 16;            // b*3 + k
    const int b  = vv / 3;
    const int k  = vv - b * 3;

    const size_t PLANE4 = (size_t)NBATCH * NS * 16;
    float4* pd = (float4*)out + (size_t)(3 + k) * PLANE4 + ((size_t)b * NS + n) * 16 + f4;

    const int Tk = 512 >> k;
    if (n >= Tk) { *pd = f40(); return; }

    const float4* lo2b = (const float4*)lo2g + (size_t)b * 1024 * 16 + f4;
    float4 lo = f40(), hi = f40();

    if (k == 0) {
        // det3/lo3: plain 8-tap over lo2
        if (n >= 2 && n <= 509) {
            const float4* p0 = lo2b + (size_t)(2 * n - 3) * 16;
#pragma unroll
            for (int t = 0; t < 8; ++t) {
                float4 v = __ldg(p0 + t * 16);
                const float c0 = cH0[t], c1 = cH1[t];
                lo.x = fmaf(c0, v.x, lo.x); lo.y = fmaf(c0, v.y, lo.y);
                lo.z = fmaf(c0, v.z, lo.z); lo.w = fmaf(c0, v.w, lo.w);
                hi.x = fmaf(c1, v.x, hi.x); hi.y = fmaf(c1, v.y, hi.y);
                hi.z = fmaf(c1, v.z, hi.z); hi.w = fmaf(c1, v.w, hi.w);
            }
        } else {
#pragma unroll
            for (int t = 0; t < 8; ++t) {
                float4 v = lo2_at(lo2b, 2 * n + t - 3);
                const float c0 = cH0[t], c1 = cH1[t];
                lo.x = fmaf(c0, v.x, lo.x); lo.y = fmaf(c0, v.y, lo.y);
                lo.z = fmaf(c0, v.z, lo.z); lo.w = fmaf(c0, v.w, lo.w);
                hi.x = fmaf(c1, v.x, hi.x); hi.y = fmaf(c1, v.y, hi.y);
                hi.z = fmaf(c1, v.z, hi.z); hi.w = fmaf(c1, v.w, hi.w);
            }
        }
    } else if (k == 1) {
        // det4/lo4: 22-tap composite (interior) or exact cascade (edge)
        if (n >= 3 && n <= 252) {
            const float4* p0 = lo2b + (size_t)(4 * n - 9) * 16;
#pragma unroll 11
            for (int u = 0; u < 22; ++u) {
                float4 v = __ldg(p0 + u * 16);
                const float c0 = __ldg(g_C2 + u), c1 = __ldg(g_D2 + u);
                lo.x = fmaf(c0, v.x, lo.x); lo.y = fmaf(c0, v.y, lo.y);
                lo.z = fmaf(c0, v.z, lo.z); lo.w = fmaf(c0, v.w, lo.w);
                hi.x = fmaf(c1, v.x, hi.x); hi.y = fmaf(c1, v.y, hi.y);
                hi.z = fmaf(c1, v.z, hi.z); hi.w = fmaf(c1, v.w, hi.w);
            }
        } else {
#pragma unroll
            for (int s = 0; s < 8; ++s) {
                float4 w = lo3_at(lo2b, 2 * n + s - 3);
                const float c0 = cH0[s], c1 = cH1[s];
                lo.x = fmaf(c0, w.x, lo.x); lo.y = fmaf(c0, w.y, lo.y);
                lo.z = fmaf(c0, w.z, lo.z); lo.w = fmaf(c0, w.w, lo.w);
                hi.x = fmaf(c1, w.x, hi.x); hi.y = fmaf(c1, w.y, hi.y);
                hi.z = fmaf(c1, w.z, hi.z); hi.w = fmaf(c1, w.w, hi.w);
            }
        }
    } else {
        // det5/lo5: 50-tap composite (interior) or exact cascade (edge)
        if (n >= 3 && n <= 124) {
            const float4* p0 = lo2b + (size_t)(8 * n - 21) * 16;
#pragma unroll 10
            for (int u = 0; u < 50; ++u) {
                float4 v = __ldg(p0 + u * 16);
                const float c0 = __ldg(g_C3 + u), c1 = __ldg(g_D3 + u);
                lo.x = fmaf(c0, v.x, lo.x); lo.y = fmaf(c0, v.y, lo.y);
                lo.z = fmaf(c0, v.z, lo.z); lo.w = fmaf(c0, v.w, lo.w);
                hi.x = fmaf(c1, v.x, hi.x); hi.y = fmaf(c1, v.y, hi.y);
                hi.z = fmaf(c1, v.z, hi.z); hi.w = fmaf(c1, v.w, hi.w);
            }
        } else {
#pragma unroll
            for (int r = 0; r < 8; ++r) {
                float4 w = lo4_at(lo2b, 2 * n + r - 3);
                const float c0 = cH0[r], c1 = cH1[r];
                lo.x = fmaf(c0, w.x, lo.x); lo.y = fmaf(c0, w.y, lo.y);
                lo.z = fmaf(c0, w.z, lo.z); lo.w = fmaf(c0, w.w, lo.w);
                hi.x = fmaf(c1, w.x, hi.x); hi.y = fmaf(c1, w.y, hi.y);
                hi.z = fmaf(c1, w.z, hi.z); hi.w = fmaf(c1, w.w, hi.w);
            }
        }
    }

    // per-feature activity mask: det index = k+2; populated iff k+2 < lf
    {
        const int f = f4 * 4;
        if (k + 2 >= level_of(__ldg(scores + f + 0))) hi.x = 0.f;
        if (k + 2 >= level_of(__ldg(scores + f + 1))) hi.y = 0.f;
        if (k + 2 >= level_of(__ldg(scores + f + 2))) hi.z = 0.f;
        if (k + 2 >= level_of(__ldg(scores + f + 3))) hi.w = 0.f;
    }
    *pd = hi;

    if (k == 0)      ((float4*)lo3g)[((size_t)b * 512 + n) * 16 + f4] = lo;
    else if (k == 1) ((float4*)lo4g)[((size_t)b * 256 + n) * 16 + f4] = lo;
    else             ((float4*)lo5g)[((size_t)b * 128 + n) * 16 + f4] = lo;
}

// ---------------- final: approx (0), high_freq (6), low_freq (7) ----------------
__global__ void __launch_bounds__(TPB)
final_kernel(float* __restrict__ out, const float* __restrict__ scores)
{
    int idx = blockIdx.x * TPB + threadIdx.x;
    const int f4 = idx & 15;
    const int s  = (idx >> 4) & (NS - 1);
    const int b  = idx >> 16;

    const size_t PLANE4 = (size_t)NBATCH * NS * 16;
    const size_t row4   = ((size_t)b * NS + s) * 16 + f4;

    float4 h = f40();
#pragma unroll
    for (int i = 0; i < 5; ++i) {
        if (s < (2048 >> i)) {
            float4 d = __ldg((const float4*)out + (1 + i) * PLANE4 + row4);
            h.x += d.x; h.y += d.y; h.z += d.z; h.w += d.w;
        }
    }
    ((float4*)out)[6 * PLANE4 + row4] = h;

    const size_t offs[4] = { OFF_LO2, OFF_LO3, OFF_LO4, OFF_LO5 };
    const int f = f4 * 4;
    float av[4];
#pragma unroll
    for (int j = 0; j < 4; ++j) {
        int k = level_of(__ldg(scores + f + j)) - 2;     // 0..3
        int T = 1024 >> k;
        av[j] = (s < T)
            ? __ldg(g_scratch + offs[k] + ((size_t)b * T + s) * 64 + f + j)
            : 0.f;
    }
    float4 a = make_float4(av[0], av[1], av[2], av[3]);
    ((float4*)out)[row4] = a;               // approx
    ((float4*)out)[7 * PLANE4 + row4] = a;  // low_freq
}

extern "C" void kernel_launch(void* const* d_in, const int* in_sizes, int n_in,
                              void* d_out, int out_size)
{
    const float* x      = (const float*)d_in[0];
    const float* scores = (const float*)d_in[1];
    float* out          = (float*)d_out;

    float* scratch;
    cudaGetSymbolAddress((void**)&scratch, g_scratch);
    float* lo1 = scratch + OFF_LO1;
    float* lo2 = scratch + OFF_LO2;
    float* lo3 = scratch + OFF_LO3;
    float* lo4 = scratch + OFF_LO4;
    float* lo5 = scratch + OFF_LO5;

    const size_t PLANE = (size_t)NBATCH * NS * 64;
    const int grid = (NBATCH * NS * 16) / TPB;          // 8192 blocks

    init_filters<<<1, 32>>>();
    level_kernel<4096><<<grid, TPB>>>(x,   lo1, out + 1 * PLANE);
    level_kernel<2048><<<grid, TPB>>>(lo1, lo2, out + 2 * PLANE);
    mega345_kernel<<<3 * grid, TPB>>>(lo2, lo3, lo4, lo5, out, scores);
    final_kernel<<<grid, TPB>>>(out, scores);
}

// round 16
// speedup vs baseline: 1.1665x; 1.0890x over previous
#include <cuda_runtime.h>

#define NS 4096
#define NBATCH 32
#define TPB 256

// pywt db4 dec filters, time-reversed (cross-correlation form)
__device__ __constant__ float cH0[8] = {
     0.23037781330885523f,  0.7148465705525415f,   0.6308807679295904f,
    -0.02798376941698385f, -0.18703481171888114f,  0.030841381835986965f,
     0.032883011666982945f, -0.010597401784997278f };
__device__ __constant__ float cH1[8] = {
    -0.010597401784997278f, -0.032883011666982945f, 0.030841381835986965f,
     0.18703481171888114f,  -0.02798376941698385f,  -0.6308807679295904f,
     0.7148465705525415f,   -0.23037781330885523f };

// Lowpass scratch planes, (B, T_k, 64) contiguous.
__device__ float g_scratch[8126464];
#define OFF_LO1 0
#define OFF_LO2 4194304
#define OFF_LO3 6291456
#define OFF_LO4 7340032
#define OFF_LO5 7864320

__device__ __forceinline__ int level_of(float sc) {
    int l = 2 + (int)rintf(sc * 3.0f);          // round-half-even, matches jnp.round
    return l < 2 ? 2 : (l > 5 ? 5 : l);
}

// ---------------- pure streaming zero-fill of ALL detail tails ----------------
// Runs on a forked stream, concurrent with the conv chain (disjoint rows).
// Thread = (b, s, f4), 1 float4 each, lane-interleaved -> perfectly coalesced.
__global__ void __launch_bounds__(TPB)
zero_kernel(float4* __restrict__ out4)
{
    int idx = blockIdx.x * TPB + threadIdx.x;
    const int f4 = idx & 15;
    const int s  = (idx >> 4) & (NS - 1);
    const int b  = idx >> 16;

    if (s < 128) return;
    const size_t PLANE4 = (size_t)NBATCH * NS * 16;
    const size_t row4   = ((size_t)b * NS + s) * 16 + f4;
    const float4 z = make_float4(0.f, 0.f, 0.f, 0.f);

    out4[5 * PLANE4 + row4] = z;             // det5 tail: s >= 128
    if (s <  256) return;
    out4[4 * PLANE4 + row4] = z;             // det4 tail: s >= 256
    if (s <  512) return;
    out4[3 * PLANE4 + row4] = z;             // det3 tail: s >= 512
    if (s < 1024) return;
    out4[2 * PLANE4 + row4] = z;             // det2 tail: s >= 1024
    if (s < 2048) return;
    out4[1 * PLANE4 + row4] = z;             // det1 tail: s >= 2048
}

// ---------------- one analysis level, coefficient rows ONLY ----------------
// Proven R13 conv body (1 float4/thread, MLP-8 branchless interior).
template <int TIN, int DET>
__global__ void __launch_bounds__(TPB)
conv_kernel(const float* __restrict__ in, float* __restrict__ loOut,
            float* __restrict__ det, const float* __restrict__ scores)
{
    constexpr int TOUT = TIN / 2;
    constexpr int LOG  = (TIN == 4096) ? 11 : (TIN == 2048) ? 10 :
                         (TIN == 1024) ?  9 : (TIN ==  512) ?  8 : 7;
    int idx = blockIdx.x * TPB + threadIdx.x;
    const int f4 = idx & 15;
    const int n  = (idx >> 4) & (TOUT - 1);
    const int b  = idx >> (4 + LOG);

    const float4* pin = (const float4*)in + (size_t)b * TIN * 16 + f4;
    float4 lo = make_float4(0.f, 0.f, 0.f, 0.f);
    float4 hi = make_float4(0.f, 0.f, 0.f, 0.f);

    if (n >= 2 && n < TOUT - 2) {
        const float4* p0 = pin + (size_t)(2 * n - 3) * 16;
        float4 v[8];
#pragma unroll
        for (int t = 0; t < 8; ++t) v[t] = __ldg(p0 + t * 16);
#pragma unroll
        for (int t = 0; t < 8; ++t) {
            const float c0 = cH0[t], c1 = cH1[t];
            lo.x = fmaf(c0, v[t].x, lo.x); lo.y = fmaf(c0, v[t].y, lo.y);
            lo.z = fmaf(c0, v[t].z, lo.z); lo.w = fmaf(c0, v[t].w, lo.w);
            hi.x = fmaf(c1, v[t].x, hi.x); hi.y = fmaf(c1, v[t].y, hi.y);
            hi.z = fmaf(c1, v[t].z, hi.z); hi.w = fmaf(c1, v[t].w, hi.w);
        }
    } else {
#pragma unroll
        for (int t = 0; t < 8; ++t) {
            int r = 2 * n + t - 3;
            if (r >= 0 && r < TIN) {
                float4 v = __ldg(pin + (size_t)r * 16);
                const float c0 = cH0[t], c1 = cH1[t];
                lo.x = fmaf(c0, v.x, lo.x); lo.y = fmaf(c0, v.y, lo.y);
                lo.z = fmaf(c0, v.z, lo.z); lo.w = fmaf(c0, v.w, lo.w);
                hi.x = fmaf(c1, v.x, hi.x); hi.y = fmaf(c1, v.y, hi.y);
                hi.z = fmaf(c1, v.z, hi.z); hi.w = fmaf(c1, v.w, hi.w);
            }
        }
    }

    if (DET >= 2) {                 // per-feature activity mask (det 0,1 always on)
        const int f = f4 * 4;
        if (DET >= level_of(__ldg(scores + f + 0))) hi.x = 0.f;
        if (DET >= level_of(__ldg(scores + f + 1))) hi.y = 0.f;
        if (DET >= level_of(__ldg(scores + f + 2))) hi.z = 0.f;
        if (DET >= level_of(__ldg(scores + f + 3))) hi.w = 0.f;
    }

    ((float4*)loOut)[((size_t)b * TOUT + n) * 16 + f4] = lo;
    ((float4*)det)[((size_t)b * NS + n) * 16 + f4] = hi;
}

// ---------------- final: approx (0), high_freq (6), low_freq (7) ----------------
__global__ void __launch_bounds__(TPB)
final_kernel(float* __restrict__ out, const float* __restrict__ scores)
{
    int idx = blockIdx.x * TPB + threadIdx.x;
    const int f4 = idx & 15;
    const int s  = (idx >> 4) & (NS - 1);
    const int b  = idx >> 16;

    const size_t PLANE4 = (size_t)NBATCH * NS * 16;
    const size_t row4   = ((size_t)b * NS + s) * 16 + f4;

    // high_freq = sum of masked detail prefixes (det_k zero for s >= T_k)
    float4 h = make_float4(0.f, 0.f, 0.f, 0.f);
#pragma unroll
    for (int i = 0; i < 5; ++i) {
        if (s < (2048 >> i)) {
            float4 d = __ldg((const float4*)out + (1 + i) * PLANE4 + row4);
            h.x += d.x; h.y += d.y; h.z += d.z; h.w += d.w;
        }
    }
    ((float4*)out)[6 * PLANE4 + row4] = h;

    // approx: per-feature selected lowpass level
    const size_t offs[4] = { OFF_LO2, OFF_LO3, OFF_LO4, OFF_LO5 };
    const int f = f4 * 4;
    float av[4];
#pragma unroll
    for (int j = 0; j < 4; ++j) {
        int k = level_of(__ldg(scores + f + j)) - 2;     // 0..3
        int T = 1024 >> k;
        av[j] = (s < T)
            ? __ldg(g_scratch + offs[k] + ((size_t)b * T + s) * 64 + f + j)
            : 0.f;
    }
    float4 a = make_float4(av[0], av[1], av[2], av[3]);
    ((float4*)out)[row4] = a;               // approx
    ((float4*)out)[7 * PLANE4 + row4] = a;  // low_freq
}

extern "C" void kernel_launch(void* const* d_in, const int* in_sizes, int n_in,
                              void* d_out, int out_size)
{
    const float* x      = (const float*)d_in[0];
    const float* scores = (const float*)d_in[1];
    float* out          = (float*)d_out;

    float* scratch;
    cudaGetSymbolAddress((void**)&scratch, g_scratch);
    float* lo1 = scratch + OFF_LO1;
    float* lo2 = scratch + OFF_LO2;
    float* lo3 = scratch + OFF_LO3;
    float* lo4 = scratch + OFF_LO4;
    float* lo5 = scratch + OFF_LO5;

    const size_t PLANE = (size_t)NBATCH * NS * 64;

    // Fresh side stream + events per call (kernel_launch runs only a couple of
    // times; never destroyed -> no destroy-during-capture hazard, no statics).
    cudaStream_t s2;
    cudaStreamCreateWithFlags(&s2, cudaStreamNonBlocking);
    cudaEvent_t eFork, eJoin;
    cudaEventCreateWithFlags(&eFork, cudaEventDisableTiming);
    cudaEventCreateWithFlags(&eJoin, cudaEventDisableTiming);

    // fork: tail-zeroing runs concurrently with the conv chain (disjoint rows)
    cudaEventRecord(eFork, 0);
    cudaStreamWaitEvent(s2, eFork, 0);
    zero_kernel<<<(NBATCH * NS * 16) / TPB, TPB, 0, s2>>>((float4*)out);

    // conv chain on the default stream, prefix-only grids
    conv_kernel<4096, 0><<<(NBATCH * 2048 * 16) / TPB, TPB>>>(x,   lo1, out + 1 * PLANE, scores);
    conv_kernel<2048, 1><<<(NBATCH * 1024 * 16) / TPB, TPB>>>(lo1, lo2, out + 2 * PLANE, scores);
    conv_kernel<1024, 2><<<(NBATCH *  512 * 16) / TPB, TPB>>>(lo2, lo3, out + 3 * PLANE, scores);
    conv_kernel< 512, 3><<<(NBATCH *  256 * 16) / TPB, TPB>>>(lo3, lo4, out + 4 * PLANE, scores);
    conv_kernel< 256, 4><<<(NBATCH *  128 * 16) / TPB, TPB>>>(lo4, lo5, out + 5 * PLANE, scores);

    // join, then final (needs det planes incl. tails + all lo scratch)
    cudaEventRecord(eJoin, s2);
    cudaStreamWaitEvent(0, eJoin, 0);
    final_kernel<<<(NBATCH * NS * 16) / TPB, TPB>>>(out, scores);
}